// round 1
// baseline (speedup 1.0000x reference)
#include <cuda_runtime.h>
#include <cuda_bf16.h>

// ICRewardModel: out[b] = sum_s sigmoid(x[b,s,:]·W[0,:]+b0) * (x[b,s,:]·W[1,:]+b1) * (s < lengths[b])
// x: (16, 4096, 1024) fp32.  Memory-bound; skip all tokens with s >= lengths[b].

#define B_DIM 16
#define S_DIM 4096
#define D_DIM 1024
#define TOKENS_PER_BLOCK 32
#define THREADS 256
#define WARPS (THREADS / 32)

__global__ void zero_out_kernel(float* __restrict__ out) {
    if (threadIdx.x < B_DIM) out[threadIdx.x] = 0.0f;
}

__global__ __launch_bounds__(THREADS) void icrm_kernel(
    const float* __restrict__ x,
    const float* __restrict__ W,
    const float* __restrict__ bias,
    const int*   __restrict__ lengths,
    float*       __restrict__ out)
{
    __shared__ float4 w0s[D_DIM / 4];
    __shared__ float4 w1s[D_DIM / 4];
    __shared__ float  warp_acc[WARPS];

    const int batch = blockIdx.y;
    const int len   = lengths[batch];
    const int s0    = blockIdx.x * TOKENS_PER_BLOCK;
    if (s0 >= len) return;  // uniform across block: masked tokens never loaded

    // Stage W (2 x 1024 fp32 = 8 KB) into shared
    for (int i = threadIdx.x; i < D_DIM / 4; i += THREADS) {
        w0s[i] = reinterpret_cast<const float4*>(W)[i];
        w1s[i] = reinterpret_cast<const float4*>(W + D_DIM)[i];
    }
    __syncthreads();

    const float b0 = bias[0];
    const float b1 = bias[1];
    const int wid  = threadIdx.x >> 5;
    const int lane = threadIdx.x & 31;
    const int s_end = min(s0 + TOKENS_PER_BLOCK, len);

    float acc = 0.0f;

    for (int s = s0 + wid; s < s_end; s += WARPS) {
        const float4* xrow = reinterpret_cast<const float4*>(
            x + ((size_t)batch * S_DIM + s) * D_DIM);

        float d0 = 0.0f, d1 = 0.0f;
        #pragma unroll
        for (int k = 0; k < D_DIM / (4 * 32); k++) {   // 8 iterations
            const int idx = k * 32 + lane;
            float4 v = xrow[idx];
            float4 a = w0s[idx];
            float4 c = w1s[idx];
            d0 = fmaf(v.x, a.x, d0); d0 = fmaf(v.y, a.y, d0);
            d0 = fmaf(v.z, a.z, d0); d0 = fmaf(v.w, a.w, d0);
            d1 = fmaf(v.x, c.x, d1); d1 = fmaf(v.y, c.y, d1);
            d1 = fmaf(v.z, c.z, d1); d1 = fmaf(v.w, c.w, d1);
        }

        // warp reduction of both dots
        #pragma unroll
        for (int off = 16; off > 0; off >>= 1) {
            d0 += __shfl_xor_sync(0xffffffffu, d0, off);
            d1 += __shfl_xor_sync(0xffffffffu, d1, off);
        }

        if (lane == 0) {
            float g = 1.0f / (1.0f + __expf(-(d0 + b0)));
            acc += g * (d1 + b1);
        }
    }

    // block reduction: one atomic per block
    if (lane == 0) warp_acc[wid] = acc;
    __syncthreads();
    if (threadIdx.x == 0) {
        float total = 0.0f;
        #pragma unroll
        for (int w = 0; w < WARPS; w++) total += warp_acc[w];
        atomicAdd(out + batch, total);
    }
}

extern "C" void kernel_launch(void* const* d_in, const int* in_sizes, int n_in,
                              void* d_out, int out_size)
{
    const float* x       = (const float*)d_in[0];
    const float* W       = (const float*)d_in[1];
    const float* bias    = (const float*)d_in[2];
    const int*   lengths = (const int*)d_in[3];
    float*       out     = (float*)d_out;

    zero_out_kernel<<<1, 32>>>(out);

    dim3 grid(S_DIM / TOKENS_PER_BLOCK, B_DIM);  // (128, 16)
    icrm_kernel<<<grid, THREADS>>>(x, W, bias, lengths, out);
}

// round 4
// speedup vs baseline: 1.1538x; 1.1538x over previous
#include <cuda_runtime.h>
#include <cuda_bf16.h>

// ICRewardModel: out[b] = sum_s sigmoid(x[b,s,:]·W[0,:]+b0) * (x[b,s,:]·W[1,:]+b1) * (s < lengths[b])
// x: (16, 4096, 1024) fp32. Memory-bound; masked tokens are never loaded.
// R2 kernel, third submission (two broker-side container failures, no bench data):
// __launch_bounds__(256,4) to force <=64 regs (4 blocks/SM, occ 24%->48%),
// front-batched 8x LDG.128 per token (MLP=8), __ldcs streaming loads.

#define B_DIM 16
#define S_DIM 4096
#define D_DIM 1024
#define TOKENS_PER_BLOCK 32
#define THREADS 256
#define WARPS (THREADS / 32)

__global__ void zero_out_kernel(float* __restrict__ out) {
    if (threadIdx.x < B_DIM) out[threadIdx.x] = 0.0f;
}

__global__ __launch_bounds__(THREADS, 4) void icrm_kernel(
    const float* __restrict__ x,
    const float* __restrict__ W,
    const float* __restrict__ bias,
    const int*   __restrict__ lengths,
    float*       __restrict__ out)
{
    __shared__ float4 w0s[D_DIM / 4];
    __shared__ float4 w1s[D_DIM / 4];
    __shared__ float  warp_acc[WARPS];

    const int batch = blockIdx.y;
    const int len   = lengths[batch];
    const int s0    = blockIdx.x * TOKENS_PER_BLOCK;
    if (s0 >= len) return;  // uniform: masked tokens never touch DRAM

    // Stage W (8 KB) into shared
    for (int i = threadIdx.x; i < D_DIM / 4; i += THREADS) {
        w0s[i] = reinterpret_cast<const float4*>(W)[i];
        w1s[i] = reinterpret_cast<const float4*>(W + D_DIM)[i];
    }
    __syncthreads();

    const float b0 = bias[0];
    const float b1 = bias[1];
    const int wid  = threadIdx.x >> 5;
    const int lane = threadIdx.x & 31;
    const int s_end = min(s0 + TOKENS_PER_BLOCK, len);

    float acc = 0.0f;

    for (int s = s0 + wid; s < s_end; s += WARPS) {
        const float4* xrow = reinterpret_cast<const float4*>(
            x + ((size_t)batch * S_DIM + s) * D_DIM);

        // Front-batch all 8 row loads: 8 independent LDG.E.128.CS in flight
        float4 v[8];
        #pragma unroll
        for (int k = 0; k < 8; k++) {
            v[k] = __ldcs(&xrow[k * 32 + lane]);
        }

        float d0 = 0.0f, d1 = 0.0f;
        #pragma unroll
        for (int k = 0; k < 8; k++) {
            const int idx = k * 32 + lane;
            float4 a = w0s[idx];
            d0 = fmaf(v[k].x, a.x, d0); d0 = fmaf(v[k].y, a.y, d0);
            d0 = fmaf(v[k].z, a.z, d0); d0 = fmaf(v[k].w, a.w, d0);
            float4 c = w1s[idx];
            d1 = fmaf(v[k].x, c.x, d1); d1 = fmaf(v[k].y, c.y, d1);
            d1 = fmaf(v[k].z, c.z, d1); d1 = fmaf(v[k].w, c.w, d1);
        }

        // warp reduction of both dots
        #pragma unroll
        for (int off = 16; off > 0; off >>= 1) {
            d0 += __shfl_xor_sync(0xffffffffu, d0, off);
            d1 += __shfl_xor_sync(0xffffffffu, d1, off);
        }

        if (lane == 0) {
            float g = 1.0f / (1.0f + __expf(-(d0 + b0)));
            acc += g * (d1 + b1);
        }
    }

    // block reduction: one atomic per block
    if (lane == 0) warp_acc[wid] = acc;
    __syncthreads();
    if (threadIdx.x == 0) {
        float total = 0.0f;
        #pragma unroll
        for (int w = 0; w < WARPS; w++) total += warp_acc[w];
        atomicAdd(out + batch, total);
    }
}

extern "C" void kernel_launch(void* const* d_in, const int* in_sizes, int n_in,
                              void* d_out, int out_size)
{
    const float* x       = (const float*)d_in[0];
    const float* W       = (const float*)d_in[1];
    const float* bias    = (const float*)d_in[2];
    const int*   lengths = (const int*)d_in[3];
    float*       out     = (float*)d_out;

    zero_out_kernel<<<1, 32>>>(out);

    dim3 grid(S_DIM / TOKENS_PER_BLOCK, B_DIM);  // (128, 16)
    icrm_kernel<<<grid, THREADS>>>(x, W, bias, lengths, out);
}